// round 3
// baseline (speedup 1.0000x reference)
#include <cuda_runtime.h>

// Blocks_86096914416144 — SNN block scan, R3:
//  * 32-thread CTAs (1024 CTAs) for near-perfect SM load balance
//    (R2's 512x64 left 68 SMs with 33% extra work).
//  * Carry spike flags / maskf / decay-count out of the store loop instead of
//    recomputing from z at the head (-~24 instrs/iter).
//  * p^decay_steps via per-thread smem table (replaces 16-instr select chain).
//  * Streaming cache hints (__ldcs/__stcs) — all data is touch-once.
// FP operation ordering identical to R2 (rel_err 0.0).

#define T_LEN   1024
#define TB      8
#define NBLK    (T_LEN / TB)      // 128
#define BATCH   32
#define NOUT    1024
#define BN      (BATCH * NOUT)    // 32768
#define CTA     32

__global__ __launch_bounds__(CTA)
void blocks_snn_kernel(const float* __restrict__ x,
                       const float* __restrict__ beta_raw,
                       const float* __restrict__ p_raw,
                       const float* __restrict__ b_raw,
                       float* __restrict__ out)
{
    __shared__ float ptab[CTA * (TB + 1)];   // per-thread p^0..p^8 (powf-exact)

    const int tid = blockIdx.x * CTA + threadIdx.x;   // 0..32767
    const int n   = tid & (NOUT - 1);

    const float beta  = fminf(fmaxf(beta_raw[n], 0.001f), 0.999f);
    const float p     = fminf(fmaxf(fabsf(p_raw[n]), 0.0f), 0.999f);
    const float bb    = fminf(fmaxf(fabsf(b_raw[n]), 0.001f), 1.0f);
    const float inv_p = 1.0f / p;

    float bpow[TB];
    bpow[0] = 1.0f;
    #pragma unroll
    for (int k = 1; k < TB; k++) bpow[k] = powf(beta, (float)k);

    float ppow[TB + 1];
    ppow[0] = 1.0f;
    #pragma unroll
    for (int k = 1; k <= TB; k++) ppow[k] = powf(p, (float)k);

    float* myptab = &ptab[threadIdx.x * (TB + 1)];
    #pragma unroll
    for (int k = 0; k <= TB; k++) myptab[k] = ppow[k];
    __syncwarp();

    // carry state
    float z[TB];                       // z_new from previous block
    float sp[TB];                      // (z == 1) flags from previous block
    #pragma unroll
    for (int t = 0; t < TB; t++) { z[t] = 0.0f; sp[t] = 0.0f; }
    float maskf = 0.0f;                // any spike in previous block
    int   ds    = 0;                   // count(z > 1) from previous block
    float a     = 0.0f;
    float vmem  = 0.0f;

    const float* xp = x + tid;
    float*       op = out + tid;

    // 4-slot register ring, prefetch 3 blocks ahead (streaming loads)
    float buf[4][TB];
    #pragma unroll
    for (int pb = 0; pb < 3; pb++) {
        const float* xb = xp + (size_t)pb * TB * BN;
        #pragma unroll
        for (int t = 0; t < TB; t++) buf[pb][t] = __ldcs(xb + t * BN);
    }

    #pragma unroll 1
    for (int g = 0; g < NBLK / 4; g++) {
        #pragma unroll
        for (int u = 0; u < 4; u++) {
            const int blk = 4 * g + u;

            // prefetch blk+3 into the slot freed last iteration
            if (blk + 3 < NBLK) {
                const float* xb = xp + (size_t)(blk + 3) * TB * BN;
                #pragma unroll
                for (int t = 0; t < TB; t++)
                    buf[(u + 3) & 3][t] = __ldcs(xb + t * BN);
            }
            const float* xc = buf[u & 3];

            // ---- adaptation update (sp, ds, maskf carried from last iter) ----
            float a_at = 0.0f;
            #pragma unroll
            for (int t = 0; t < TB; t++)
                if (sp[t] != 0.0f) a_at += ppow[t + 1] * a;   // same order as R2
            a_at += inv_p;

            const float pds   = myptab[ds];                   // powf(p, ds), exact
            const float new_a = a_at * pds;
            a = (maskf != 0.0f) ? new_a : (ppow[TB] * a);

            // ---- refractory masking + membrane carry-in ----
            const float v_init = vmem * (1.0f - maskf);
            float cur[TB];
            #pragma unroll
            for (int t = 0; t < TB; t++)
                cur[t] = (z[t] < maskf) ? 0.0f : xc[t];
            cur[0] = cur[0] + beta * v_init;

            // ---- causal decayed sum + threshold (ordering preserved) ----
            float f[TB];
            float mlast = 0.0f;
            #pragma unroll
            for (int t = 0; t < TB; t++) {
                float m = 0.0f;
                #pragma unroll
                for (int s = 0; s <= t; s++)
                    m += bpow[t - s] * cur[s];
                const float vth = 1.0f + bb * (ppow[t + 1] * a);
                f[t] = ((m - vth) > 0.0f) ? 1.0f : 0.0f;
                if (t == TB - 1) mlast = m;
            }

            // ---- z = double cumsum; emit spikes; fold next-iter flags ----
            float* ob = op + (size_t)blk * TB * BN;
            float c = 0.0f, zr = 0.0f;
            float nmask = 0.0f;
            int   nds   = 0;
            #pragma unroll
            for (int t = 0; t < TB; t++) {
                c  += f[t];
                zr += c;
                z[t] = zr;
                const float spike = (zr == 1.0f) ? 1.0f : 0.0f;
                sp[t] = spike;
                nmask = fmaxf(nmask, spike);
                if (zr > 1.0f) nds++;
                __stcs(ob + t * BN, spike);
            }
            maskf = nmask;
            ds    = nds;
            vmem  = mlast;
        }
    }
}

extern "C" void kernel_launch(void* const* d_in, const int* in_sizes, int n_in,
                              void* d_out, int out_size)
{
    const float* x        = (const float*)d_in[0];
    const float* beta_raw = (const float*)d_in[1];
    const float* p_raw    = (const float*)d_in[2];
    const float* b_raw    = (const float*)d_in[3];
    float* out = (float*)d_out;

    blocks_snn_kernel<<<BN / CTA, CTA>>>(x, beta_raw, p_raw, b_raw, out);
}

// round 4
// speedup vs baseline: 1.0525x; 1.0525x over previous
#include <cuda_runtime.h>

// Blocks_86096914416144 — SNN block scan, R4:
// R3's instruction cuts + 128-thread CTAs.
// R3 lesson: 32-thread CTAs put every warp at wid=0 -> all warps on SMSP 0
// (SMSP = wid%4), serializing issue on one of four schedulers. 128-thread
// CTAs spread wid 0..3 across all 4 SMSPs.
// FP operation ordering identical to R2/R3 (rel_err 0.0).

#define T_LEN   1024
#define TB      8
#define NBLK    (T_LEN / TB)      // 128
#define BATCH   32
#define NOUT    1024
#define BN      (BATCH * NOUT)    // 32768
#define CTA     128

__global__ __launch_bounds__(CTA)
void blocks_snn_kernel(const float* __restrict__ x,
                       const float* __restrict__ beta_raw,
                       const float* __restrict__ p_raw,
                       const float* __restrict__ b_raw,
                       float* __restrict__ out)
{
    __shared__ float ptab[CTA * (TB + 1)];   // per-thread p^0..p^8 (powf-exact)

    const int tid = blockIdx.x * CTA + threadIdx.x;   // 0..32767
    const int n   = tid & (NOUT - 1);

    const float beta  = fminf(fmaxf(beta_raw[n], 0.001f), 0.999f);
    const float p     = fminf(fmaxf(fabsf(p_raw[n]), 0.0f), 0.999f);
    const float bb    = fminf(fmaxf(fabsf(b_raw[n]), 0.001f), 1.0f);
    const float inv_p = 1.0f / p;

    float bpow[TB];
    bpow[0] = 1.0f;
    #pragma unroll
    for (int k = 1; k < TB; k++) bpow[k] = powf(beta, (float)k);

    float ppow[TB + 1];
    ppow[0] = 1.0f;
    #pragma unroll
    for (int k = 1; k <= TB; k++) ppow[k] = powf(p, (float)k);

    float* myptab = &ptab[threadIdx.x * (TB + 1)];
    #pragma unroll
    for (int k = 0; k <= TB; k++) myptab[k] = ppow[k];
    __syncwarp();

    // carry state
    float z[TB];                       // z_new from previous block
    float sp[TB];                      // (z == 1) flags from previous block
    #pragma unroll
    for (int t = 0; t < TB; t++) { z[t] = 0.0f; sp[t] = 0.0f; }
    float maskf = 0.0f;                // any spike in previous block
    int   ds    = 0;                   // count(z > 1) from previous block
    float a     = 0.0f;
    float vmem  = 0.0f;

    const float* xp = x + tid;
    float*       op = out + tid;

    // 4-slot register ring, prefetch 3 blocks ahead (streaming loads)
    float buf[4][TB];
    #pragma unroll
    for (int pb = 0; pb < 3; pb++) {
        const float* xb = xp + (size_t)pb * TB * BN;
        #pragma unroll
        for (int t = 0; t < TB; t++) buf[pb][t] = __ldcs(xb + t * BN);
    }

    #pragma unroll 1
    for (int g = 0; g < NBLK / 4; g++) {
        #pragma unroll
        for (int u = 0; u < 4; u++) {
            const int blk = 4 * g + u;

            // prefetch blk+3 into the slot freed last iteration
            if (blk + 3 < NBLK) {
                const float* xb = xp + (size_t)(blk + 3) * TB * BN;
                #pragma unroll
                for (int t = 0; t < TB; t++)
                    buf[(u + 3) & 3][t] = __ldcs(xb + t * BN);
            }
            const float* xc = buf[u & 3];

            // ---- adaptation update (sp, ds, maskf carried from last iter) ----
            float a_at = 0.0f;
            #pragma unroll
            for (int t = 0; t < TB; t++)
                if (sp[t] != 0.0f) a_at += ppow[t + 1] * a;   // same order as R2
            a_at += inv_p;

            const float pds   = myptab[ds];                   // p^ds, powf-exact
            const float new_a = a_at * pds;
            a = (maskf != 0.0f) ? new_a : (ppow[TB] * a);

            // ---- refractory masking + membrane carry-in ----
            const float v_init = vmem * (1.0f - maskf);
            float cur[TB];
            #pragma unroll
            for (int t = 0; t < TB; t++)
                cur[t] = (z[t] < maskf) ? 0.0f : xc[t];
            cur[0] = cur[0] + beta * v_init;

            // ---- causal decayed sum + threshold (ordering preserved) ----
            float f[TB];
            float mlast = 0.0f;
            #pragma unroll
            for (int t = 0; t < TB; t++) {
                float m = 0.0f;
                #pragma unroll
                for (int s = 0; s <= t; s++)
                    m += bpow[t - s] * cur[s];
                const float vth = 1.0f + bb * (ppow[t + 1] * a);
                f[t] = ((m - vth) > 0.0f) ? 1.0f : 0.0f;
                if (t == TB - 1) mlast = m;
            }

            // ---- z = double cumsum; emit spikes; fold next-iter flags ----
            float* ob = op + (size_t)blk * TB * BN;
            float c = 0.0f, zr = 0.0f;
            float nmask = 0.0f;
            int   nds   = 0;
            #pragma unroll
            for (int t = 0; t < TB; t++) {
                c  += f[t];
                zr += c;
                z[t] = zr;
                const float spike = (zr == 1.0f) ? 1.0f : 0.0f;
                sp[t] = spike;
                nmask = fmaxf(nmask, spike);
                if (zr > 1.0f) nds++;
                __stcs(ob + t * BN, spike);
            }
            maskf = nmask;
            ds    = nds;
            vmem  = mlast;
        }
    }
}

extern "C" void kernel_launch(void* const* d_in, const int* in_sizes, int n_in,
                              void* d_out, int out_size)
{
    const float* x        = (const float*)d_in[0];
    const float* beta_raw = (const float*)d_in[1];
    const float* p_raw    = (const float*)d_in[2];
    const float* b_raw    = (const float*)d_in[3];
    float* out = (float*)d_out;

    blocks_snn_kernel<<<BN / CTA, CTA>>>(x, beta_raw, p_raw, b_raw, out);
}

// round 5
// speedup vs baseline: 1.1649x; 1.1068x over previous
#include <cuda_runtime.h>

// Blocks_86096914416144 — SNN block scan, R5:
// EXACT R2 body (proven 59.9us, rel_err 0.0), single change: CTA 64 -> 128.
// R2 analysis: with 64-thr CTAs all warps sit at wid%4 in {0,1} -> only 2 of 4
// SMSPs used; per-active-SMSP issue ~93% (reported 46.4% is a 4-SMSP average).
// 128-thr CTAs spread warps across all 4 schedulers with identical wave
// balance. No other change (R3/R4 body edits are under suspicion).

#define T_LEN   1024
#define TB      8
#define NBLK    (T_LEN / TB)      // 128
#define BATCH   32
#define NOUT    1024
#define BN      (BATCH * NOUT)    // 32768
#define CTA     128

struct LaneState {
    float z[TB];
    float a;
    float vmem;
};

__device__ __forceinline__
void step_block(LaneState& st,
                const float* __restrict__ xc,
                float* __restrict__ ob,
                float beta, float bb, float inv_p,
                const float* __restrict__ bpow,
                const float* __restrict__ ppow)
{
    // sg (prev spikes) and maskf
    float sg[TB];
    float maskf = 0.0f;
    #pragma unroll
    for (int t = 0; t < TB; t++) {
        sg[t] = (st.z[t] == 1.0f) ? 1.0f : 0.0f;
        if (sg[t] != 0.0f) maskf = 1.0f;
    }

    // adaptation: a_at_spike = sum_t p^(t+1)*a*sg[t] + 1/p
    float a_at = 0.0f;
    #pragma unroll
    for (int t = 0; t < TB; t++)
        if (sg[t] != 0.0f) a_at += ppow[t + 1] * st.a;
    a_at += inv_p;

    int ds = 0;                         // decay_steps = count(z > 1)
    #pragma unroll
    for (int t = 0; t < TB; t++)
        if (st.z[t] > 1.0f) ds++;

    float pds = ppow[0];
    #pragma unroll
    for (int k = 1; k <= TB; k++)
        if (ds == k) pds = ppow[k];

    const float new_a = a_at * pds;
    st.a = (maskf != 0.0f) ? new_a : (ppow[TB] * st.a);

    // refractory masking + membrane carry-in
    const float v_init = st.vmem * (1.0f - maskf);
    float cur[TB];
    #pragma unroll
    for (int t = 0; t < TB; t++)
        cur[t] = (st.z[t] < maskf) ? 0.0f : xc[t];
    cur[0] = cur[0] + beta * v_init;

    // causal decayed sum + threshold
    float f[TB];
    float mlast = 0.0f;
    #pragma unroll
    for (int t = 0; t < TB; t++) {
        float m = 0.0f;
        #pragma unroll
        for (int s = 0; s <= t; s++)
            m += bpow[t - s] * cur[s];
        const float vth = 1.0f + bb * (ppow[t + 1] * st.a);
        f[t] = ((m - vth) > 0.0f) ? 1.0f : 0.0f;
        if (t == TB - 1) mlast = m;
    }

    // z = double cumsum of f; emit spikes (z == 1)
    float c = 0.0f, zr = 0.0f;
    #pragma unroll
    for (int t = 0; t < TB; t++) {
        c  += f[t];
        zr += c;
        st.z[t] = zr;
        ob[t * BN] = (zr == 1.0f) ? 1.0f : 0.0f;
    }

    st.vmem = mlast;
}

__global__ __launch_bounds__(CTA)
void blocks_snn_kernel(const float* __restrict__ x,
                       const float* __restrict__ beta_raw,
                       const float* __restrict__ p_raw,
                       const float* __restrict__ b_raw,
                       float* __restrict__ out)
{
    const int tid = blockIdx.x * CTA + threadIdx.x;   // 0..32767
    const int n   = tid & (NOUT - 1);

    const float beta  = fminf(fmaxf(beta_raw[n], 0.001f), 0.999f);
    const float p     = fminf(fmaxf(fabsf(p_raw[n]), 0.0f), 0.999f);
    const float bb    = fminf(fmaxf(fabsf(b_raw[n]), 0.001f), 1.0f);
    const float inv_p = 1.0f / p;

    float bpow[TB];
    bpow[0] = 1.0f;
    #pragma unroll
    for (int k = 1; k < TB; k++) bpow[k] = powf(beta, (float)k);

    float ppow[TB + 1];
    ppow[0] = 1.0f;
    #pragma unroll
    for (int k = 1; k <= TB; k++) ppow[k] = powf(p, (float)k);

    LaneState st;
    #pragma unroll
    for (int t = 0; t < TB; t++) st.z[t] = 0.0f;
    st.a = 0.0f;
    st.vmem = 0.0f;

    const float* xp = x + tid;
    float*       op = out + tid;

    // 4-slot register ring, prefetch 3 blocks ahead
    float buf[4][TB];
    #pragma unroll
    for (int pb = 0; pb < 3; pb++) {
        const float* xb = xp + (size_t)pb * TB * BN;
        #pragma unroll
        for (int t = 0; t < TB; t++) buf[pb][t] = xb[t * BN];
    }

    #pragma unroll 1
    for (int g = 0; g < NBLK / 4; g++) {
        #pragma unroll
        for (int u = 0; u < 4; u++) {
            const int blk = 4 * g + u;
            if (blk + 3 < NBLK) {
                const float* xb = xp + (size_t)(blk + 3) * TB * BN;
                #pragma unroll
                for (int t = 0; t < TB; t++)
                    buf[(u + 3) & 3][t] = xb[t * BN];
            }
            step_block(st, buf[u & 3], op + (size_t)blk * TB * BN,
                       beta, bb, inv_p, bpow, ppow);
        }
    }
}

extern "C" void kernel_launch(void* const* d_in, const int* in_sizes, int n_in,
                              void* d_out, int out_size)
{
    const float* x        = (const float*)d_in[0];
    const float* beta_raw = (const float*)d_in[1];
    const float* p_raw    = (const float*)d_in[2];
    const float* b_raw    = (const float*)d_in[3];
    float* out = (float*)d_out;

    blocks_snn_kernel<<<BN / CTA, CTA>>>(x, beta_raw, p_raw, b_raw, out);
}